// round 1
// baseline (speedup 1.0000x reference)
#include <cuda_runtime.h>
#include <cuda_bf16.h>
#include <math.h>

#define NN 100000
#define EE 3200000

// ---- scratch (device globals; allocation-free) ----
__device__ float  g_deg[NN];
__device__ float  g_dinv[NN];
__device__ float4 g_xw[NN];     // x @ W1            [N,4]
__device__ float4 g_acc1[NN];   // conv1 scatter acc [N,4]
__device__ float4 g_h2w[NN];    // h1 @ [Wmu|Wls]    [N,4]
__device__ float4 g_acc2[NN];   // conv2 scatter acc [N,4]
__device__ int    g_src[EE];
__device__ int    g_dst[EE];
__device__ int    g_is64;

// ---- detect whether edge_index arrived as int64 or int32 ----
// int64 little-endian with values < 2^31  =>  all odd 32-bit words are 0.
__global__ void k_detect(const unsigned int* __restrict__ ei) {
    if (threadIdx.x == 0) {
        int all0 = 1;
        #pragma unroll 1
        for (int i = 0; i < 64; ++i) {
            if (ei[2 * i + 1] != 0u) { all0 = 0; break; }
        }
        g_is64 = all0;
    }
}

// ---- init: deg=1 (self loop), zero accumulators ----
__global__ void k_init(int n) {
    int i = blockIdx.x * blockDim.x + threadIdx.x;
    if (i < n) {
        g_deg[i]  = 1.0f;
        g_acc1[i] = make_float4(0.f, 0.f, 0.f, 0.f);
        g_acc2[i] = make_float4(0.f, 0.f, 0.f, 0.f);
    }
}

// ---- decode edges to int32 + degree count ----
__global__ void k_edges(const void* __restrict__ ei, int e) {
    int i = blockIdx.x * blockDim.x + threadIdx.x;
    if (i >= e) return;
    int s, d;
    if (g_is64) {
        const long long* p = (const long long*)ei;
        s = (int)p[i];
        d = (int)p[(long long)e + i];
    } else {
        const int* p = (const int*)ei;
        s = p[i];
        d = p[e + i];
    }
    g_src[i] = s;
    g_dst[i] = d;
    atomicAdd(&g_deg[d], 1.0f);
}

__global__ void k_dinv(int n) {
    int i = blockIdx.x * blockDim.x + threadIdx.x;
    if (i < n) g_dinv[i] = rsqrtf(g_deg[i]);   // deg >= 1 always (self loop)
}

// ---- xw = x @ W1 : one warp per row, HBM-bound ----
__global__ void __launch_bounds__(256) k_gemm(const float* __restrict__ x,
                                              const float* __restrict__ W1, int n) {
    __shared__ float4 Ws[512];                 // W1 [512,4] as 512 x float4
    int t = threadIdx.x;
    const float4* W4 = (const float4*)W1;
    Ws[t]       = W4[t];
    Ws[t + 256] = W4[t + 256];
    __syncthreads();

    int warp = t >> 5, lane = t & 31;
    int row  = blockIdx.x * 8 + warp;
    if (row >= n) return;

    const float4* xr = (const float4*)(x + (size_t)row * 512);
    float4 acc = make_float4(0.f, 0.f, 0.f, 0.f);
    #pragma unroll
    for (int i = 0; i < 4; ++i) {
        float4 xv = __ldg(&xr[i * 32 + lane]);
        int k = i * 128 + lane * 4;
        float4 w0 = Ws[k], w1 = Ws[k + 1], w2 = Ws[k + 2], w3 = Ws[k + 3];
        acc.x += xv.x * w0.x + xv.y * w1.x + xv.z * w2.x + xv.w * w3.x;
        acc.y += xv.x * w0.y + xv.y * w1.y + xv.z * w2.y + xv.w * w3.y;
        acc.z += xv.x * w0.z + xv.y * w1.z + xv.z * w2.z + xv.w * w3.z;
        acc.w += xv.x * w0.w + xv.y * w1.w + xv.z * w2.w + xv.w * w3.w;
    }
    #pragma unroll
    for (int off = 16; off; off >>= 1) {
        acc.x += __shfl_xor_sync(0xffffffffu, acc.x, off);
        acc.y += __shfl_xor_sync(0xffffffffu, acc.y, off);
        acc.z += __shfl_xor_sync(0xffffffffu, acc.z, off);
        acc.w += __shfl_xor_sync(0xffffffffu, acc.w, off);
    }
    if (lane == 0) g_xw[row] = acc;
}

// ---- conv scatter: one vector atomic per edge ----
__global__ void k_conv1(int e) {
    int i = blockIdx.x * blockDim.x + threadIdx.x;
    if (i >= e) return;
    int s = g_src[i], d = g_dst[i];
    float w = g_dinv[s] * g_dinv[d];
    float4 v = g_xw[s];
    atomicAdd(&g_acc1[d], make_float4(w * v.x, w * v.y, w * v.z, w * v.w));
}

// ---- finalize conv1: +self-loop +bias, relu, then h1 @ [Wmu|Wls] (4x4) ----
__global__ void k_fin1(const float* __restrict__ b1,
                       const float* __restrict__ Wmu,
                       const float* __restrict__ Wls, int n) {
    int i = blockIdx.x * blockDim.x + threadIdx.x;
    if (i >= n) return;
    float di = g_dinv[i];
    float w  = di * di;
    float4 a  = g_acc1[i];
    float4 xv = g_xw[i];
    float h0 = fmaxf(a.x + w * xv.x + b1[0], 0.f);
    float h1 = fmaxf(a.y + w * xv.y + b1[1], 0.f);
    float h2 = fmaxf(a.z + w * xv.z + b1[2], 0.f);
    float h3 = fmaxf(a.w + w * xv.w + b1[3], 0.f);
    float4 o;
    // W_mu, W_ls are [4,2] row-major: W[j*2 + c]
    o.x = h0 * Wmu[0] + h1 * Wmu[2] + h2 * Wmu[4] + h3 * Wmu[6];
    o.y = h0 * Wmu[1] + h1 * Wmu[3] + h2 * Wmu[5] + h3 * Wmu[7];
    o.z = h0 * Wls[0] + h1 * Wls[2] + h2 * Wls[4] + h3 * Wls[6];
    o.w = h0 * Wls[1] + h1 * Wls[3] + h2 * Wls[5] + h3 * Wls[7];
    g_h2w[i] = o;
}

__global__ void k_conv2(int e) {
    int i = blockIdx.x * blockDim.x + threadIdx.x;
    if (i >= e) return;
    int s = g_src[i], d = g_dst[i];
    float w = g_dinv[s] * g_dinv[d];
    float4 v = g_h2w[s];
    atomicAdd(&g_acc2[d], make_float4(w * v.x, w * v.y, w * v.z, w * v.w));
}

// ---- finalize conv2: +self-loop +bias, write mu then logstd ----
__global__ void k_fin2(const float* __restrict__ bmu,
                       const float* __restrict__ bls,
                       float* __restrict__ out, int n) {
    int i = blockIdx.x * blockDim.x + threadIdx.x;
    if (i >= n) return;
    float di = g_dinv[i];
    float w  = di * di;
    float4 a  = g_acc2[i];
    float4 hv = g_h2w[i];
    float2 mu, ls;
    mu.x = a.x + w * hv.x + bmu[0];
    mu.y = a.y + w * hv.y + bmu[1];
    ls.x = a.z + w * hv.z + bls[0];
    ls.y = a.w + w * hv.w + bls[1];
    ((float2*)out)[i] = mu;                       // mu [N,2]
    ((float2*)(out + 2 * (size_t)n))[i] = ls;     // logstd [N,2]
}

extern "C" void kernel_launch(void* const* d_in, const int* in_sizes, int n_in,
                              void* d_out, int out_size) {
    const float* x   = (const float*)d_in[0];
    const void*  ei  = d_in[1];
    const float* W1  = (const float*)d_in[2];
    const float* b1  = (const float*)d_in[3];
    const float* Wmu = (const float*)d_in[4];
    const float* bmu = (const float*)d_in[5];
    const float* Wls = (const float*)d_in[6];
    const float* bls = (const float*)d_in[7];

    int n = in_sizes[0] / 512;   // 100000
    int e = in_sizes[1] / 2;     // 3200000

    int nb = (n + 255) / 256;
    int eb = (e + 255) / 256;

    k_detect<<<1, 32>>>((const unsigned int*)ei);
    k_init<<<nb, 256>>>(n);
    k_edges<<<eb, 256>>>(ei, e);
    k_dinv<<<nb, 256>>>(n);
    k_gemm<<<(n + 7) / 8, 256>>>(x, W1, n);
    k_conv1<<<eb, 256>>>(e);
    k_fin1<<<nb, 256>>>(b1, Wmu, Wls, n);
    k_conv2<<<eb, 256>>>(e);
    k_fin2<<<nb, 256>>>(bmu, bls, (float*)d_out, n);
}